// round 12
// baseline (speedup 1.0000x reference)
#include <cuda_runtime.h>

#define NQ    12
#define DIM   4096
#define NT    1024

// ================= compile-time GF(2) plan =================
__host__ __device__ constexpr unsigned Gm_c(unsigned j) {
    unsigned r = (j ^ (j >> 1)) & 0xFFFu;
    r ^= (j >> 11) & 1u;
    return r;
}
__host__ __device__ constexpr unsigned Fm_c(unsigned k) {
    unsigned p = k;
    p ^= p >> 1; p ^= p >> 2; p ^= p >> 4; p ^= p >> 8;
    p &= 0xFFFu;
    return (p & 0xFFEu) | ((p ^ (k >> 11)) & 1u);
}
__host__ __device__ constexpr unsigned GmPow(unsigned v, int n) {
    for (int i = 0; i < n; i++) v = Gm_c(v);
    return v;
}
__host__ __device__ constexpr unsigned FmPow(unsigned v, int n) {
    for (int i = 0; i < n; i++) v = Fm_c(v);
    return v;
}
__host__ __device__ constexpr unsigned rowOf(int pw, int q) {
    unsigned r = 0;
    for (int j = 0; j < 12; j++)
        r |= ((FmPow(1u << j, pw) >> q) & 1u) << j;
    return r;
}
__host__ __device__ constexpr unsigned m1c(int blk, int q) { return GmPow(1u << q, blk); }
__host__ __device__ constexpr unsigned R1c(int blk, int q) { return rowOf(blk, q); }
__host__ __device__ constexpr unsigned mEc(int blk, int e) {
    unsigned a = e < 11 ? 11 - e : 11;
    unsigned b = e < 11 ? 10 - e : 0;
    return GmPow((1u << a) | (1u << b), blk);
}
__host__ __device__ constexpr unsigned XEc(int blk, int e) {
    int a = e < 11 ? 11 - e : 11;
    int b = e < 11 ? 10 - e : 0;
    return rowOf(blk, a) ^ rowOf(blk, b);
}
__host__ __device__ constexpr unsigned RMc(int i) { return rowOf(3, 11 - i); }
__host__ __device__ constexpr int topbit(unsigned m) { int h = 0; while (m >>= 1) h++; return h; }
__host__ __device__ constexpr int imin(int a, int b) { return a < b ? a : b; }
__host__ __device__ constexpr int imax(int a, int b) { return a > b ? a : b; }
__host__ __device__ constexpr int parc(unsigned x) { int c = 0; while (x) { c ^= (int)(x & 1u); x >>= 1; } return c; }

// ================= device math helpers =================
struct CM { float2 m[4]; };

__device__ __forceinline__ float2 cxmul(float2 a, float2 b) {
    return make_float2(a.x*b.x - a.y*b.y, a.x*b.y + a.y*b.x);
}
__device__ __forceinline__ float2 cxadd(float2 a, float2 b) {
    return make_float2(a.x + b.x, a.y + b.y);
}
__device__ __forceinline__ CM mm(const CM& A, const CM& B) {
    CM C;
#pragma unroll
    for (int i = 0; i < 2; i++)
#pragma unroll
        for (int j = 0; j < 2; j++)
            C.m[i*2+j] = cxadd(cxmul(A.m[i*2+0], B.m[0*2+j]),
                               cxmul(A.m[i*2+1], B.m[1*2+j]));
    return C;
}
__device__ __forceinline__ CM RX(float t) {
    float s, c; sincosf(0.5f*t, &s, &c);
    CM M;
    M.m[0] = make_float2(c,0.f);  M.m[1] = make_float2(0.f,-s);
    M.m[2] = make_float2(0.f,-s); M.m[3] = make_float2(c,0.f);
    return M;
}
__device__ __forceinline__ CM RY(float t) {
    float s, c; sincosf(0.5f*t, &s, &c);
    CM M;
    M.m[0] = make_float2(c,0.f); M.m[1] = make_float2(-s,0.f);
    M.m[2] = make_float2(s,0.f); M.m[3] = make_float2(c,0.f);
    return M;
}
__device__ __forceinline__ CM RZ(float t) {
    float s, c; sincosf(0.5f*t, &s, &c);
    CM M;
    M.m[0] = make_float2(c,-s);    M.m[1] = make_float2(0.f,0.f);
    M.m[2] = make_float2(0.f,0.f); M.m[3] = make_float2(c,s);
    return M;
}
__device__ __forceinline__ void apply2(const float2 g[4], float2 &a0, float2 &a1) {
    float2 n0, n1;
    n0.x = g[0].x*a0.x - g[0].y*a0.y + g[1].x*a1.x - g[1].y*a1.y;
    n0.y = g[0].x*a0.y + g[0].y*a0.x + g[1].x*a1.y + g[1].y*a1.x;
    n1.x = g[2].x*a0.x - g[2].y*a0.y + g[3].x*a1.x - g[3].y*a1.y;
    n1.y = g[2].x*a0.y + g[2].y*a0.x + g[3].x*a1.y + g[3].y*a1.x;
    a0 = n0; a1 = n1;
}
__device__ __forceinline__ void applyMix(float c, float ss, float2 &a, float2 &b) {
    float2 na, nb;
    na.x = c*a.x - ss*b.y;  na.y = c*a.y + ss*b.x;
    nb.x = c*b.x - ss*a.y;  nb.y = c*b.y + ss*a.x;
    a = na; b = nb;
}
__device__ __forceinline__ unsigned insert1(unsigned i, int h) {
    return ((i >> h) << (h + 1)) | (i & ((1u << h) - 1u));
}
__device__ __forceinline__ unsigned insert2(unsigned i, int lo, int hi) {
    unsigned p = ((i >> lo) << (lo + 1)) | (i & ((1u << lo) - 1u));
    p = ((p >> hi) << (hi + 1)) | (p & ((1u << hi) - 1u));
    return p;
}
__device__ __forceinline__ int par(unsigned x) { return __popc(x) & 1; }

// ================= lane gates (masks within bits 0..4) =================
template<int BLK, int Q>
__device__ __forceinline__ void shflGate(const float2 (*gt)[4], float2 (&V)[4], unsigned base)
{
    constexpr unsigned mc = m1c(BLK, Q), R = R1c(BLK, Q);
    static_assert((mc & ~0x1Fu) == 0, "lane mask");
    const unsigned bit = (unsigned)par(base & R);
    const float2 gd = bit ? gt[Q][3] : gt[Q][0];
    const float2 go = bit ? gt[Q][2] : gt[Q][1];
#pragma unroll
    for (int r = 0; r < 4; r++) {
        float px = __shfl_xor_sync(0xffffffffu, V[r].x, mc);
        float py = __shfl_xor_sync(0xffffffffu, V[r].y, mc);
        float2 nv;
        nv.x = gd.x*V[r].x - gd.y*V[r].y + go.x*px - go.y*py;
        nv.y = gd.x*V[r].y + gd.y*V[r].x + go.x*py + go.y*px;
        V[r] = nv;
    }
}

template<int BLK, int E>
__device__ __forceinline__ void shflEdge(const float* sCb, const float* sSb,
                                         float2 (&V)[4], unsigned p)
{
    constexpr unsigned mc = mEc(BLK, E);
    static_assert((mc & ~0x1Fu) == 0, "lane edge mask");
    const float cc = sCb[E], sv = sSb[E];
    float ss;
    if constexpr (BLK == 1) {
        ss = -sv;
    } else {
        constexpr unsigned X = XEc(2, E);
        ss = par(p & X) ? -sv : sv;
    }
#pragma unroll
    for (int r = 0; r < 4; r++) {
        float px = __shfl_xor_sync(0xffffffffu, V[r].x, mc);
        float py = __shfl_xor_sync(0xffffffffu, V[r].y, mc);
        float2 nv;
        nv.x = cc*V[r].x - ss*py;
        nv.y = cc*V[r].y + ss*px;
        V[r] = nv;
    }
}

// ================= quad sweep: 1 quad/thread, 1024 threads =================
// LSET: 0 none; 1 -> lanes q0,q1; 2 -> q2,q3; 3 -> q4
template<int BLK, int QA, int QB, int LSET, bool SYNC>
__device__ __forceinline__ void quadSweep(const float2 (*gt)[4], float2* amp, unsigned t)
{
    constexpr unsigned mA = m1c(BLK, QA), RA = R1c(BLK, QA);
    constexpr unsigned mB = m1c(BLK, QB), RB = R1c(BLK, QB);
    constexpr int lo = imin(topbit(mA), topbit(mB));
    constexpr int hi = imax(topbit(mA), topbit(mB));
    unsigned p = insert2(t, lo, hi);
    unsigned base = p;
    if (par(p & RA)) base ^= mA;
    if (par(p & RB)) base ^= mB;
    float2 V[4];
    V[0] = amp[base];      V[1] = amp[base ^ mA];
    V[2] = amp[base ^ mB]; V[3] = amp[base ^ mA ^ mB];
    {
        float2 gA[4], gB[4];
#pragma unroll
        for (int k = 0; k < 4; k++) { gA[k] = gt[QA][k]; gB[k] = gt[QB][k]; }
        apply2(gA, V[0], V[1]); apply2(gA, V[2], V[3]);
        apply2(gB, V[0], V[2]); apply2(gB, V[1], V[3]);
    }
    if constexpr (LSET == 1) {
        shflGate<BLK,0>(gt, V, base);
        shflGate<BLK,1>(gt, V, base);
    } else if constexpr (LSET == 2) {
        shflGate<BLK,2>(gt, V, base);
        shflGate<BLK,3>(gt, V, base);
    } else if constexpr (LSET == 3) {
        shflGate<BLK,4>(gt, V, base);
    }
    amp[base] = V[0];      amp[base ^ mA] = V[1];
    amp[base ^ mB] = V[2]; amp[base ^ mA ^ mB] = V[3];
    if constexpr (SYNC) __syncthreads();
}

// ================= pair sweep (single gate), 2 pairs/thread =================
template<int BLK, int Q, bool MEASURE, bool SYNC>
__device__ __forceinline__ void pairSweep(const float2 (*gt)[4], float2* amp, unsigned t,
                                          float (&acc)[NQ])
{
    constexpr unsigned m = m1c(BLK, Q), R = R1c(BLK, Q);
    constexpr int h = topbit(m);
    float2 g[4];
#pragma unroll
    for (int k = 0; k < 4; k++) g[k] = gt[Q][k];
    constexpr unsigned RMv[NQ] = {
        RMc(0), RMc(1), RMc(2),  RMc(3),
        RMc(4), RMc(5), RMc(6),  RMc(7),
        RMc(8), RMc(9), RMc(10), RMc(11)
    };
#pragma unroll
    for (int k = 0; k < 2; k++) {
        unsigned p = insert1(t + k*NT, h);
        unsigned base = par(p & R) ? (p ^ m) : p;
        float2 V0 = amp[base], V1 = amp[base ^ m];
        apply2(g, V0, V1);
        if constexpr (MEASURE) {
            float pr0 = V0.x*V0.x + V0.y*V0.y;
            float pr1 = V1.x*V1.x + V1.y*V1.y;
            unsigned i0 = base, i1 = base ^ m;
#pragma unroll
            for (int i = 0; i < NQ; i++) {
                acc[i] += par(i0 & RMv[i]) ? -pr0 : pr0;
                acc[i] += par(i1 & RMv[i]) ? -pr1 : pr1;
            }
        } else {
            amp[base] = V0; amp[base ^ m] = V1;
        }
    }
    if constexpr (SYNC) __syncthreads();
}

// ================= Ising quad sweep =================
// LSET: 0 none; 1 -> lane edges e7,e8; 2 -> e9,e10
template<int BLK, int E1, int E2, int LSET, bool SYNC>
__device__ __forceinline__ void isingSweep(const float* sCb, const float* sSb,
                                           float2* amp, unsigned t)
{
    constexpr unsigned m1m = mEc(BLK, E1), m2m = mEc(BLK, E2);
    const float c1 = sCb[E1], s1 = sSb[E1];
    const float c2 = sCb[E2], s2 = sSb[E2];
    constexpr int lo = imin(topbit(m1m), topbit(m2m));
    constexpr int hi = imax(topbit(m1m), topbit(m2m));
    unsigned p = insert2(t, lo, hi);
    const unsigned iA = p ^ m1m, iB = p ^ m2m, iC = p ^ m1m ^ m2m;
    float2 V[4];
    V[0] = amp[p]; V[1] = amp[iA]; V[2] = amp[iB]; V[3] = amp[iC];
    if constexpr (BLK == 1) {
        applyMix(c1, -s1, V[0], V[1]); applyMix(c1, -s1, V[2], V[3]);
        applyMix(c2, -s2, V[0], V[2]); applyMix(c2, -s2, V[1], V[3]);
    } else {
        constexpr unsigned X1 = XEc(2, E1), X2 = XEc(2, E2);
        constexpr unsigned adj1 = (unsigned)parc(m2m & X1);
        constexpr unsigned adj2 = (unsigned)parc(m1m & X2);
        unsigned t1 = (unsigned)par(p & X1);
        applyMix(c1, t1 ? -s1 : s1, V[0], V[1]);
        applyMix(c1, (t1 ^ adj1) ? -s1 : s1, V[2], V[3]);
        unsigned t2 = (unsigned)par(p & X2);
        applyMix(c2, t2 ? -s2 : s2, V[0], V[2]);
        applyMix(c2, (t2 ^ adj2) ? -s2 : s2, V[1], V[3]);
    }
    if constexpr (LSET == 1) {
        shflEdge<BLK,7>(sCb, sSb, V, p);
        shflEdge<BLK,8>(sCb, sSb, V, p);
    } else if constexpr (LSET == 2) {
        shflEdge<BLK,9>(sCb, sSb, V, p);
        shflEdge<BLK,10>(sCb, sSb, V, p);
    }
    amp[p] = V[0]; amp[iA] = V[1]; amp[iB] = V[2]; amp[iC] = V[3];
    if constexpr (SYNC) __syncthreads();
}

// ================= edge quad (e11, e0): both masks topbit 11, reduced basis =================
template<int BLK, bool SYNC>
__device__ __forceinline__ void quadEdge(const float* sCb, const float* sSb,
                                         float2* amp, unsigned t)
{
    constexpr unsigned m1 = mEc(BLK, 11), m2 = mEc(BLK, 0);
    constexpr int hi = topbit(m1);
    constexpr unsigned b2 = (topbit(m2) == hi) ? (m1 ^ m2) : m2;
    constexpr int lo = topbit(b2);
    static_assert(lo < hi, "basis");
    const float c1 = sCb[11], s1 = sSb[11];
    const float c2 = sCb[0],  s2 = sSb[0];
    unsigned p = insert2(t, lo, hi);
    float2 V0 = amp[p],      V1 = amp[p ^ m1];
    float2 V2 = amp[p ^ m2], V3 = amp[p ^ m1 ^ m2];
    if constexpr (BLK == 1) {
        applyMix(c1, -s1, V0, V1); applyMix(c1, -s1, V2, V3);
        applyMix(c2, -s2, V0, V2); applyMix(c2, -s2, V1, V3);
    } else {
        constexpr unsigned X1 = XEc(2, 11), X2 = XEc(2, 0);
        constexpr unsigned adj1 = (unsigned)parc(m2 & X1);
        constexpr unsigned adj2 = (unsigned)parc(m1 & X2);
        unsigned t1 = (unsigned)par(p & X1);
        unsigned t2 = (unsigned)par(p & X2);
        applyMix(c1, t1 ? -s1 : s1, V0, V1);
        applyMix(c1, (t1 ^ adj1) ? -s1 : s1, V2, V3);
        applyMix(c2, t2 ? -s2 : s2, V0, V2);
        applyMix(c2, (t2 ^ adj2) ? -s2 : s2, V1, V3);
    }
    amp[p] = V0;      amp[p ^ m1] = V1;
    amp[p ^ m2] = V2; amp[p ^ m1 ^ m2] = V3;
    if constexpr (SYNC) __syncthreads();
}

// ================= kernel =================
__global__ void __launch_bounds__(NT, 1)
qsim_kernel(const float* __restrict__ data,
            const float* __restrict__ es,
            const float* __restrict__ eb,
            const float* __restrict__ eta,
            const float* __restrict__ ew_zz,
            const float* __restrict__ ew_xx,
            const float* __restrict__ ew_yy,
            const float* __restrict__ nb_z,
            const float* __restrict__ nb_x,
            const float* __restrict__ nb_y,
            const float* __restrict__ rots,
            float* __restrict__ out)
{
    __shared__ float2 amp[DIM];
    __shared__ float2 gT1[3][NQ][4];
    __shared__ float2 gT2[3][NQ][4];
    __shared__ float  sC[3][NQ], sS[3][NQ], sH0[NQ];
    __shared__ float  red[NT/32][NQ];

    const int b = blockIdx.x;
    const unsigned t = threadIdx.x;

    // ---- gate tables, split across 72 threads ----
    if (t < 36) {
        const int blk = t / 12, q = t % 12;
        float d  = data[b*NQ + q];
        float ax = es[q*3+0]*d + eb[q*3+0];
        float ay = es[q*3+1]*d + eb[q*3+1];
        float az = es[q*3+2]*d + eb[q*3+2];
        CM M;
        if (blk == 0)      M = mm(RZ(az), mm(RY(ay), RX(ax)));
        else if (blk == 1) M = mm(RY(ay), RX(ax));
        else               M = mm(RZ(az), RY(ay));
#pragma unroll
        for (int k = 0; k < 4; k++) gT1[blk][q][k] = M.m[k];

        float ew = (blk == 0) ? ew_zz[q] : (blk == 1) ? ew_xx[q] : ew_yy[q];
        float h = 0.5f * eta[blk] * ew;
        float s, c; sincosf(h, &s, &c);
        sC[blk][q] = c; sS[blk][q] = s;
        if (blk == 0) sH0[q] = h;
    } else if (t < 72) {
        const int blk = (t - 36) / 12, q = (t - 36) % 12;
        float bias = (blk == 0) ? nb_z[q] : (blk == 1) ? nb_x[q] : nb_y[q];
        CM Mb = (blk == 0) ? RZ(bias) : (blk == 1) ? RX(bias) : RY(bias);
        const float* rr = rots + blk*(NQ*3) + q*3;
        CM M2 = mm(RZ(rr[2]), mm(RY(rr[1]), mm(RX(rr[0]), Mb)));
#pragma unroll
        for (int k = 0; k < 4; k++) gT2[blk][q][k] = M2.m[k];
    }
    __syncthreads();

    float accDummy[NQ];

    // ---- blk0: closed-form init (enc product + ZZ phase) + bias q10,q11 (register) + lanes q0,q1 ----
    {
        float2 prod = make_float2(1.0f, 0.0f);
#pragma unroll
        for (int q = 0; q < 10; q++) {
            float2 f = ((t >> q) & 1) ? gT1[0][q][2] : gT1[0][q][0];
            prod = cxmul(prod, f);
        }
        constexpr unsigned XE0v[NQ] = {
            XEc(0,0), XEc(0,1), XEc(0,2),  XEc(0,3),
            XEc(0,4), XEc(0,5), XEc(0,6),  XEc(0,7),
            XEc(0,8), XEc(0,9), XEc(0,10), XEc(0,11)
        };
        float2 V[4];
#pragma unroll
        for (int j = 0; j < 4; j++) {
            unsigned l = t + j*NT;           // bit10=j&1, bit11=j&2
            float2 v = cxmul(prod, (j & 1) ? gT1[0][10][2] : gT1[0][10][0]);
            v = cxmul(v,            (j & 2) ? gT1[0][11][2] : gT1[0][11][0]);
            float phi = 0.0f;
#pragma unroll
            for (int e = 0; e < NQ; e++)
                phi += par(l & XE0v[e]) ? sH0[e] : -sH0[e];
            float sp, cp; __sincosf(phi, &sp, &cp);
            V[j] = make_float2(v.x*cp - v.y*sp, v.x*sp + v.y*cp);
        }
        // fused bias gates on register bits (blk0 frame identity: masks = pure bits 10,11)
        {
            float2 g10[4], g11[4];
#pragma unroll
            for (int k = 0; k < 4; k++) { g10[k] = gT2[0][10][k]; g11[k] = gT2[0][11][k]; }
            apply2(g10, V[0],V[1]); apply2(g10, V[2],V[3]);
            apply2(g11, V[0],V[2]); apply2(g11, V[1],V[3]);
        }
        shflGate<0,0>(gT2[0], V, t);
        shflGate<0,1>(gT2[0], V, t);
#pragma unroll
        for (int j = 0; j < 4; j++) amp[t + j*NT] = V[j];
        __syncthreads();
    }
    // blk0 bias rest: q5,q6 + lanes q2,q3; q8,q9 + lane q4; pair q7
    quadSweep<0,5,6,2,true>(gT2[0], amp, t);
    quadSweep<0,8,9,3,true>(gT2[0], amp, t);
    pairSweep<0,7,false,true>(gT2[0], amp, t, accDummy);

    // ======== block 1 ========
    quadSweep<1,9,10,1,true>(gT1[1], amp, t);
    quadSweep<1,8,11,2,true>(gT1[1], amp, t);
    quadSweep<1,5,6 ,3,true>(gT1[1], amp, t);
    pairSweep<1,7,false,true>(gT1[1], amp, t, accDummy);
    isingSweep<1,1,2,1,true>(sC[1], sS[1], amp, t);
    isingSweep<1,3,4,2,true>(sC[1], sS[1], amp, t);
    isingSweep<1,5,6,0,true>(sC[1], sS[1], amp, t);
    quadEdge<1,true>(sC[1], sS[1], amp, t);
    quadSweep<1,9,10,1,true>(gT2[1], amp, t);
    quadSweep<1,8,11,2,true>(gT2[1], amp, t);
    quadSweep<1,5,6 ,3,true>(gT2[1], amp, t);
    pairSweep<1,7,false,true>(gT2[1], amp, t, accDummy);

    // ======== block 2 ========
    quadSweep<2,9,10,1,true>(gT1[2], amp, t);
    quadSweep<2,8,11,2,true>(gT1[2], amp, t);
    quadSweep<2,5,6 ,3,true>(gT1[2], amp, t);
    pairSweep<2,7,false,true>(gT1[2], amp, t, accDummy);
    isingSweep<2,1,2,1,true>(sC[2], sS[2], amp, t);
    isingSweep<2,3,4,2,true>(sC[2], sS[2], amp, t);
    isingSweep<2,5,6,0,true>(sC[2], sS[2], amp, t);
    quadEdge<2,true>(sC[2], sS[2], amp, t);
    quadSweep<2,9,10,1,true>(gT2[2], amp, t);
    quadSweep<2,8,11,2,true>(gT2[2], amp, t);
    quadSweep<2,5,6 ,3,true>(gT2[2], amp, t);

    // ---- final: pair q7 (blk2 bias) fused with measurement ----
    float acc[NQ];
#pragma unroll
    for (int i = 0; i < NQ; i++) acc[i] = 0.0f;
    pairSweep<2,7,true,false>(gT2[2], amp, t, acc);

    // ---- reduction ----
#pragma unroll
    for (int off = 16; off > 0; off >>= 1)
#pragma unroll
        for (int i = 0; i < NQ; i++)
            acc[i] += __shfl_down_sync(0xffffffffu, acc[i], off);
    const int wid = t >> 5;
    if ((t & 31) == 0) {
#pragma unroll
        for (int i = 0; i < NQ; i++) red[wid][i] = acc[i];
    }
    __syncthreads();
    if (t < NQ) {
        float s = 0.0f;
#pragma unroll
        for (int w = 0; w < NT/32; w++) s += red[w][t];
        out[b*NQ + t] = s;
    }
}

extern "C" void kernel_launch(void* const* d_in, const int* in_sizes, int n_in,
                              void* d_out, int out_size) {
    const float* data   = (const float*)d_in[0];
    const float* es     = (const float*)d_in[1];
    const float* eb     = (const float*)d_in[2];
    const float* eta    = (const float*)d_in[3];
    const float* ew_zz  = (const float*)d_in[4];
    const float* ew_xx  = (const float*)d_in[5];
    const float* ew_yy  = (const float*)d_in[6];
    const float* nb_z   = (const float*)d_in[7];
    const float* nb_x   = (const float*)d_in[8];
    const float* nb_y   = (const float*)d_in[9];
    const float* rots   = (const float*)d_in[10];
    float* out = (float*)d_out;

    int B = in_sizes[0] / NQ;   // 64
    qsim_kernel<<<B, NT>>>(data, es, eb, eta, ew_zz, ew_xx, ew_yy,
                           nb_z, nb_x, nb_y, rots, out);
}

// round 13
// speedup vs baseline: 1.2796x; 1.2796x over previous
#include <cuda_runtime.h>
#include <cooperative_groups.h>
namespace cg = cooperative_groups;

#define NQ    12
#define HDIM  2048
#define NT    512

// ================= compile-time GF(2) plan =================
__host__ __device__ constexpr unsigned Gm_c(unsigned j) {
    unsigned r = (j ^ (j >> 1)) & 0xFFFu;
    r ^= (j >> 11) & 1u;
    return r;
}
__host__ __device__ constexpr unsigned Fm_c(unsigned k) {
    unsigned p = k;
    p ^= p >> 1; p ^= p >> 2; p ^= p >> 4; p ^= p >> 8;
    p &= 0xFFFu;
    return (p & 0xFFEu) | ((p ^ (k >> 11)) & 1u);
}
__host__ __device__ constexpr unsigned GmPow(unsigned v, int n) {
    for (int i = 0; i < n; i++) v = Gm_c(v);
    return v;
}
__host__ __device__ constexpr unsigned FmPow(unsigned v, int n) {
    for (int i = 0; i < n; i++) v = Fm_c(v);
    return v;
}
__host__ __device__ constexpr unsigned rowOf(int pw, int q) {
    unsigned r = 0;
    for (int j = 0; j < 12; j++)
        r |= ((FmPow(1u << j, pw) >> q) & 1u) << j;
    return r;
}
__host__ __device__ constexpr unsigned m1c(int blk, int q) { return GmPow(1u << q, blk); }
__host__ __device__ constexpr unsigned R1c(int blk, int q) { return rowOf(blk, q); }
__host__ __device__ constexpr unsigned mEc(int blk, int e) {
    unsigned a = e < 11 ? 11 - e : 11;
    unsigned b = e < 11 ? 10 - e : 0;
    return GmPow((1u << a) | (1u << b), blk);
}
__host__ __device__ constexpr unsigned XEc(int blk, int e) {
    int a = e < 11 ? 11 - e : 11;
    int b = e < 11 ? 10 - e : 0;
    return rowOf(blk, a) ^ rowOf(blk, b);
}
__host__ __device__ constexpr unsigned RMc(int i) { return rowOf(3, 11 - i); }
__host__ __device__ constexpr int topbit(unsigned m) { int h = 0; while (m >>= 1) h++; return h; }
__host__ __device__ constexpr int imin(int a, int b) { return a < b ? a : b; }
__host__ __device__ constexpr int imax(int a, int b) { return a > b ? a : b; }
__host__ __device__ constexpr int parc(unsigned x) { int c = 0; while (x) { c ^= (int)(x & 1u); x >>= 1; } return c; }

// ================= device math helpers =================
struct CM { float2 m[4]; };

__device__ __forceinline__ float2 cxmul(float2 a, float2 b) {
    return make_float2(a.x*b.x - a.y*b.y, a.x*b.y + a.y*b.x);
}
__device__ __forceinline__ float2 cxadd(float2 a, float2 b) {
    return make_float2(a.x + b.x, a.y + b.y);
}
__device__ __forceinline__ CM mm(const CM& A, const CM& B) {
    CM C;
#pragma unroll
    for (int i = 0; i < 2; i++)
#pragma unroll
        for (int j = 0; j < 2; j++)
            C.m[i*2+j] = cxadd(cxmul(A.m[i*2+0], B.m[0*2+j]),
                               cxmul(A.m[i*2+1], B.m[1*2+j]));
    return C;
}
__device__ __forceinline__ CM RX(float t) {
    float s, c; sincosf(0.5f*t, &s, &c);
    CM M;
    M.m[0] = make_float2(c,0.f);  M.m[1] = make_float2(0.f,-s);
    M.m[2] = make_float2(0.f,-s); M.m[3] = make_float2(c,0.f);
    return M;
}
__device__ __forceinline__ CM RY(float t) {
    float s, c; sincosf(0.5f*t, &s, &c);
    CM M;
    M.m[0] = make_float2(c,0.f); M.m[1] = make_float2(-s,0.f);
    M.m[2] = make_float2(s,0.f); M.m[3] = make_float2(c,0.f);
    return M;
}
__device__ __forceinline__ CM RZ(float t) {
    float s, c; sincosf(0.5f*t, &s, &c);
    CM M;
    M.m[0] = make_float2(c,-s);    M.m[1] = make_float2(0.f,0.f);
    M.m[2] = make_float2(0.f,0.f); M.m[3] = make_float2(c,s);
    return M;
}
__device__ __forceinline__ void apply2(const float2 g[4], float2 &a0, float2 &a1) {
    float2 n0, n1;
    n0.x = g[0].x*a0.x - g[0].y*a0.y + g[1].x*a1.x - g[1].y*a1.y;
    n0.y = g[0].x*a0.y + g[0].y*a0.x + g[1].x*a1.y + g[1].y*a1.x;
    n1.x = g[2].x*a0.x - g[2].y*a0.y + g[3].x*a1.x - g[3].y*a1.y;
    n1.y = g[2].x*a0.y + g[2].y*a0.x + g[3].x*a1.y + g[3].y*a1.x;
    a0 = n0; a1 = n1;
}
__device__ __forceinline__ void applyMix(float c, float ss, float2 &a, float2 &b) {
    float2 na, nb;
    na.x = c*a.x - ss*b.y;  na.y = c*a.y + ss*b.x;
    nb.x = c*b.x - ss*a.y;  nb.y = c*b.y + ss*a.x;
    a = na; b = nb;
}
__device__ __forceinline__ unsigned insert1(unsigned i, int h) {
    return ((i >> h) << (h + 1)) | (i & ((1u << h) - 1u));
}
__device__ __forceinline__ unsigned insert2(unsigned i, int lo, int hi) {
    unsigned p = ((i >> lo) << (lo + 1)) | (i & ((1u << lo) - 1u));
    p = ((p >> hi) << (hi + 1)) | (p & ((1u << hi) - 1u));
    return p;
}
__device__ __forceinline__ int par(unsigned x) { return __popc(x) & 1; }
__device__ __forceinline__ void cfma(float2& acc, float2 a, float2 b) {
    acc.x += a.x*b.x - a.y*b.y;
    acc.y += a.x*b.y + a.y*b.x;
}

// ================= lane gates on a 4-value quad (blk0 bias stage) =================
template<int BLK, int Q>
__device__ __forceinline__ void shflGate(const float2 (*gt)[4], float2 (&V)[4],
                                         unsigned base, unsigned rank)
{
    constexpr unsigned mc = m1c(BLK, Q), R = R1c(BLK, Q);
    unsigned bit = (unsigned)par(base & (R & 0x7FFu));
    if constexpr ((R >> 11) != 0) bit ^= rank;
    const float2 gd = bit ? gt[Q][3] : gt[Q][0];
    const float2 go = bit ? gt[Q][2] : gt[Q][1];
#pragma unroll
    for (int r = 0; r < 4; r++) {
        float px = __shfl_xor_sync(0xffffffffu, V[r].x, mc);
        float py = __shfl_xor_sync(0xffffffffu, V[r].y, mc);
        float2 nv;
        nv.x = gd.x*V[r].x - gd.y*V[r].y + go.x*px - go.y*py;
        nv.y = gd.x*V[r].y + gd.y*V[r].x + go.x*py + go.y*px;
        V[r] = nv;
    }
}

// lane gate on a cross-event pair (values at base and base^M12)
template<int BLK, int Q, unsigned M12>
__device__ __forceinline__ void lanePair(const float2 (*gt)[4], float2 &v0, float2 &v1,
                                         unsigned base, unsigned rank)
{
    constexpr unsigned mc = m1c(BLK, Q), R = R1c(BLK, Q);
    constexpr unsigned adj = (unsigned)parc(M12 & R & 0x7FFu);
    unsigned b0 = (unsigned)par(base & (R & 0x7FFu));
    if constexpr ((R >> 11) != 0) b0 ^= rank;
    const unsigned b1 = b0 ^ adj;
    const float2 gd0 = b0 ? gt[Q][3] : gt[Q][0];
    const float2 go0 = b0 ? gt[Q][2] : gt[Q][1];
    const float2 gd1 = b1 ? gt[Q][3] : gt[Q][0];
    const float2 go1 = b1 ? gt[Q][2] : gt[Q][1];
    float p0x = __shfl_xor_sync(0xffffffffu, v0.x, mc);
    float p0y = __shfl_xor_sync(0xffffffffu, v0.y, mc);
    float p1x = __shfl_xor_sync(0xffffffffu, v1.x, mc);
    float p1y = __shfl_xor_sync(0xffffffffu, v1.y, mc);
    float2 n0, n1;
    n0.x = gd0.x*v0.x - gd0.y*v0.y + go0.x*p0x - go0.y*p0y;
    n0.y = gd0.x*v0.y + gd0.y*v0.x + go0.x*p0y + go0.y*p0x;
    n1.x = gd1.x*v1.x - gd1.y*v1.y + go1.x*p1x - go1.y*p1y;
    n1.y = gd1.x*v1.y + gd1.y*v1.x + go1.x*p1y + go1.y*p1x;
    v0 = n0; v1 = n1;
}

template<int BLK, int E>
__device__ __forceinline__ void shflEdge(const float* sCb, const float* sSb,
                                         float2 (&V)[4], unsigned p, unsigned rank)
{
    constexpr unsigned mc = mEc(BLK, E);
    const float cc = sCb[E], sv = sSb[E];
    float ss;
    if constexpr (BLK == 1) {
        ss = -sv;
    } else {
        constexpr unsigned X = XEc(2, E);
        unsigned sg = (unsigned)par(p & (X & 0x7FFu));
        if constexpr ((X >> 11) != 0) sg ^= rank;
        ss = sg ? -sv : sv;
    }
#pragma unroll
    for (int r = 0; r < 4; r++) {
        float px = __shfl_xor_sync(0xffffffffu, V[r].x, mc);
        float py = __shfl_xor_sync(0xffffffffu, V[r].y, mc);
        float2 nv;
        nv.x = cc*V[r].x - ss*py;
        nv.y = cc*V[r].y + ss*px;
        V[r] = nv;
    }
}

// ================= quad sweeps (4 amps/thread, 512 threads) =================
// blk0-only: quad(9,10) + all 5 lane gates
template<int BLK>
__device__ __forceinline__ void sweepA1q(const float2 (*gt)[4], float2* amp,
                                         unsigned rank, unsigned t)
{
    constexpr unsigned mA = m1c(BLK, 9),  RA = R1c(BLK, 9);
    constexpr unsigned mB = m1c(BLK, 10), RB = R1c(BLK, 10);
    constexpr int lo = imin(topbit(mA), topbit(mB));
    constexpr int hi = imax(topbit(mA), topbit(mB));
    unsigned p = insert2(t, lo, hi);
    unsigned base = p;
    unsigned fA = (unsigned)par(p & (RA & 0x7FFu));
    if constexpr ((RA >> 11) != 0) fA ^= rank;
    if (fA) base ^= mA;
    unsigned fB = (unsigned)par(p & (RB & 0x7FFu));
    if constexpr ((RB >> 11) != 0) fB ^= rank;
    if (fB) base ^= mB;
    float2 V[4];
    V[0] = amp[base];      V[1] = amp[base ^ mA];
    V[2] = amp[base ^ mB]; V[3] = amp[base ^ mA ^ mB];
    {
        float2 gA[4], gB[4];
#pragma unroll
        for (int k = 0; k < 4; k++) { gA[k] = gt[9][k]; gB[k] = gt[10][k]; }
        apply2(gA, V[0], V[1]); apply2(gA, V[2], V[3]);
        apply2(gB, V[0], V[2]); apply2(gB, V[1], V[3]);
    }
    shflGate<BLK,0>(gt, V, base, rank);
    shflGate<BLK,1>(gt, V, base, rank);
    shflGate<BLK,2>(gt, V, base, rank);
    shflGate<BLK,3>(gt, V, base, rank);
    shflGate<BLK,4>(gt, V, base, rank);
    amp[base] = V[0];      amp[base ^ mA] = V[1];
    amp[base ^ mB] = V[2]; amp[base ^ mA ^ mB] = V[3];
    __syncthreads();
}

// plain quad sweep (no lanes)
template<int BLK, int QA, int QB, bool SYNC>
__device__ __forceinline__ void quadSweep(const float2 (*gt)[4], float2* amp,
                                          unsigned rank, unsigned t)
{
    constexpr unsigned mA = m1c(BLK, QA), RA = R1c(BLK, QA);
    constexpr unsigned mB = m1c(BLK, QB), RB = R1c(BLK, QB);
    constexpr int lo = imin(topbit(mA), topbit(mB));
    constexpr int hi = imax(topbit(mA), topbit(mB));
    unsigned p = insert2(t, lo, hi);
    unsigned base = p;
    unsigned fA = (unsigned)par(p & (RA & 0x7FFu));
    if constexpr ((RA >> 11) != 0) fA ^= rank;
    if (fA) base ^= mA;
    unsigned fB = (unsigned)par(p & (RB & 0x7FFu));
    if constexpr ((RB >> 11) != 0) fB ^= rank;
    if (fB) base ^= mB;
    float2 gA[4], gB[4];
#pragma unroll
    for (int k = 0; k < 4; k++) { gA[k] = gt[QA][k]; gB[k] = gt[QB][k]; }
    const unsigned i10 = base ^ mA, i01 = base ^ mB, i11 = base ^ mA ^ mB;
    float2 a00 = amp[base], a10 = amp[i10], a01 = amp[i01], a11 = amp[i11];
    apply2(gA, a00, a10); apply2(gA, a01, a11);
    apply2(gB, a00, a01); apply2(gB, a10, a11);
    amp[base] = a00; amp[i10] = a10; amp[i01] = a01; amp[i11] = a11;
    if constexpr (SYNC) __syncthreads();
}

template<int BLK, int E1, int E2, bool DOSHFL, bool SYNC>
__device__ __forceinline__ void isingSweep(const float* sCb, const float* sSb,
                                           float2* amp, unsigned rank, unsigned t)
{
    constexpr unsigned m1m = mEc(BLK, E1), m2m = mEc(BLK, E2);
    const float c1 = sCb[E1], s1 = sSb[E1];
    const float c2 = sCb[E2], s2 = sSb[E2];
    constexpr int lo = imin(topbit(m1m), topbit(m2m));
    constexpr int hi = imax(topbit(m1m), topbit(m2m));
    unsigned p = insert2(t, lo, hi);
    const unsigned iA = p ^ m1m, iB = p ^ m2m, iC = p ^ m1m ^ m2m;
    float2 V[4];
    V[0] = amp[p]; V[1] = amp[iA]; V[2] = amp[iB]; V[3] = amp[iC];
    if constexpr (BLK == 1) {
        applyMix(c1, -s1, V[0], V[1]); applyMix(c1, -s1, V[2], V[3]);
        applyMix(c2, -s2, V[0], V[2]); applyMix(c2, -s2, V[1], V[3]);
    } else {
        constexpr unsigned X1 = XEc(2, E1), X2 = XEc(2, E2);
        constexpr unsigned adj1 = (unsigned)parc(m2m & X1 & 0x7FFu);
        constexpr unsigned adj2 = (unsigned)parc(m1m & X2 & 0x7FFu);
        unsigned t1 = (unsigned)par(p & (X1 & 0x7FFu));
        if constexpr ((X1 >> 11) != 0) t1 ^= rank;
        applyMix(c1, t1 ? -s1 : s1, V[0], V[1]);
        applyMix(c1, (t1 ^ adj1) ? -s1 : s1, V[2], V[3]);
        unsigned t2 = (unsigned)par(p & (X2 & 0x7FFu));
        if constexpr ((X2 >> 11) != 0) t2 ^= rank;
        applyMix(c2, t2 ? -s2 : s2, V[0], V[2]);
        applyMix(c2, (t2 ^ adj2) ? -s2 : s2, V[1], V[3]);
    }
    if constexpr (DOSHFL) {
        shflEdge<BLK,7>(sCb, sSb, V, p, rank);
        shflEdge<BLK,8>(sCb, sSb, V, p, rank);
        shflEdge<BLK,9>(sCb, sSb, V, p, rank);
        shflEdge<BLK,10>(sCb, sSb, V, p, rank);
    }
    amp[p] = V[0]; amp[iA] = V[1]; amp[iB] = V[2]; amp[iC] = V[3];
    if constexpr (SYNC) __syncthreads();
}

// ================= cross events (now absorbing the 5 lane gates) =================
template<int BLK>
__device__ __forceinline__ void cross1q(const float2* ga, const float2 (*gt1)[4],
                                        float2*& cur, float2*& nxt,
                                        float2*& pcur, float2*& pnxt,
                                        cg::cluster_group& cl,
                                        unsigned rank, unsigned t)
{
    constexpr unsigned ma = m1c(BLK-1, 11), mb = m1c(BLK, 11);
    const float2* gb = gt1[11];
    const float2 ga_d  = rank ? ga[3] : ga[0];
    const float2 ga_o  = rank ? ga[2] : ga[1];
    const float2 ga_d2 = rank ? ga[0] : ga[3];
    const float2 ga_o2 = rank ? ga[1] : ga[2];
    const float2 gb_d  = rank ? gb[3] : gb[0];
    const float2 gb_o  = rank ? gb[2] : gb[1];
    const float2 C1 = cxmul(gb_d, ga_d);
    const float2 C2 = cxmul(gb_d, ga_o);
    const float2 C3 = cxmul(gb_o, ga_d2);
    const float2 C4 = cxmul(gb_o, ga_o2);
    constexpr unsigned m12 = (ma ^ mb) & 0x7FFu;
    constexpr int h12 = topbit(m12);
    constexpr unsigned pa = ma & 0x7FFu, pb = mb & 0x7FFu;
    cl.sync();
#pragma unroll
    for (int j = 0; j < 2; j++) {
        unsigned base = insert1(t + j*NT, h12);
        float2 r0 = cur[base],       r1 = cur[base ^ m12];
        float2 q0 = pcur[base ^ pa], q1 = pcur[base ^ pb];
        float2 o0 = make_float2(0.f, 0.f), o1 = make_float2(0.f, 0.f);
        cfma(o0, C1, r0); cfma(o0, C2, q0); cfma(o0, C3, q1); cfma(o0, C4, r1);
        cfma(o1, C1, r1); cfma(o1, C2, q1); cfma(o1, C3, q0); cfma(o1, C4, r0);
        // encoding lane gates q0..q4 (moved here from the quad(9,10) sweep)
        lanePair<BLK,0,m12>(gt1, o0, o1, base, rank);
        lanePair<BLK,1,m12>(gt1, o0, o1, base, rank);
        lanePair<BLK,2,m12>(gt1, o0, o1, base, rank);
        lanePair<BLK,3,m12>(gt1, o0, o1, base, rank);
        lanePair<BLK,4,m12>(gt1, o0, o1, base, rank);
        nxt[base] = o0; nxt[base ^ m12] = o1;
    }
    __syncthreads();
    { float2* s = cur; cur = nxt; nxt = s; }
    { float2* s = pcur; pcur = pnxt; pnxt = s; }
}

template<int BLK>
__device__ __forceinline__ void crossE(const float* sCb, const float* sSb,
                                       const float2 (*gt2)[4],
                                       float2*& cur, float2*& nxt,
                                       float2*& pcur, float2*& pnxt,
                                       cg::cluster_group& cl,
                                       unsigned rank, unsigned t)
{
    constexpr unsigned m1e = mEc(BLK, 11), m2e = mEc(BLK, 0);
    const float c1 = sCb[11], s1 = sSb[11];
    const float c2 = sCb[0],  s2 = sSb[0];
    const float cc = c1 * c2;
    constexpr unsigned X1 = XEc(2, 11), X2 = XEc(2, 0);
    constexpr int f1 = (BLK == 2) ? parc(mEc(2, 0) & XEc(2, 11) & 0xFFFu) : 0;
    constexpr unsigned m12 = (m1e ^ m2e) & 0x7FFu;
    constexpr int h12 = topbit(m12);
    constexpr unsigned p1m = m1e & 0x7FFu, p2m = m2e & 0x7FFu;
    cl.sync();
#pragma unroll
    for (int j = 0; j < 2; j++) {
        unsigned base = insert1(t + j*NT, h12);
        float2 A0 = cur[base],        A1 = cur[base ^ m12];
        float2 P1 = pcur[base ^ p1m], P2 = pcur[base ^ p2m];
        float w1, w2, w1b, w2b;
        if constexpr (BLK == 1) {
            w1 = -s1; w2 = -s2; w1b = w1; w2b = w2;
        } else {
            unsigned k12  = base | (rank << 11);
            unsigned k12b = k12 ^ m12;
            w1  = par(k12  & X1) ? -s1 : s1;
            w2  = par(k12  & X2) ? -s2 : s2;
            w1b = par(k12b & X1) ? -s1 : s1;
            w2b = par(k12b & X2) ? -s2 : s2;
        }
        float2 rA, rB;
        {
            float w1p = f1 ? -w1 : w1;
            float T4 = -(w2 * w1p);
            float k1 = c2 * w1, k2 = c1 * w2;
            rA.x = cc*A0.x - k1*P1.y - k2*P2.y + T4*A1.x;
            rA.y = cc*A0.y + k1*P1.x + k2*P2.x + T4*A1.y;
        }
        {
            float w1p = f1 ? -w1b : w1b;
            float T4 = -(w2b * w1p);
            float k1 = c2 * w1b, k2 = c1 * w2b;
            rB.x = cc*A1.x - k1*P2.y - k2*P1.y + T4*A0.x;
            rB.y = cc*A1.y + k1*P2.x + k2*P1.x + T4*A0.y;
        }
        // bias lane gates q0..q4 (moved here from the quad(9,10) bias sweep)
        lanePair<BLK,0,m12>(gt2, rA, rB, base, rank);
        lanePair<BLK,1,m12>(gt2, rA, rB, base, rank);
        lanePair<BLK,2,m12>(gt2, rA, rB, base, rank);
        lanePair<BLK,3,m12>(gt2, rA, rB, base, rank);
        lanePair<BLK,4,m12>(gt2, rA, rB, base, rank);
        nxt[base] = rA; nxt[base ^ m12] = rB;
    }
    __syncthreads();
    { float2* s = cur; cur = nxt; nxt = s; }
    { float2* s = pcur; pcur = pnxt; pnxt = s; }
}

// ================= kernel =================
__global__ void __launch_bounds__(NT, 1) __cluster_dims__(2, 1, 1)
qsim_kernel(const float* __restrict__ data,
            const float* __restrict__ es,
            const float* __restrict__ eb,
            const float* __restrict__ eta,
            const float* __restrict__ ew_zz,
            const float* __restrict__ ew_xx,
            const float* __restrict__ ew_yy,
            const float* __restrict__ nb_z,
            const float* __restrict__ nb_x,
            const float* __restrict__ nb_y,
            const float* __restrict__ rots,
            float* __restrict__ out)
{
    __shared__ float2 ampA[HDIM];
    __shared__ float2 ampB[HDIM];
    __shared__ float2 gT1[3][NQ][4];
    __shared__ float2 gT2[3][NQ][4];
    __shared__ float  sC[3][NQ], sS[3][NQ], sH0[NQ];
    __shared__ float  red[NT/32][NQ];
    __shared__ float  sums[NQ];

    cg::cluster_group cl = cg::this_cluster();
    const unsigned rank = blockIdx.x & 1u;
    const int b = blockIdx.x >> 1;
    const unsigned t = threadIdx.x;
    float2* peerA = cl.map_shared_rank(ampA, rank ^ 1u);
    float2* peerB = cl.map_shared_rank(ampB, rank ^ 1u);
    float*  psums = cl.map_shared_rank(sums, 1u);

    // ---- all gate tables upfront, 36 threads ----
    if (t < 36) {
        const int blk = t / 12, q = t % 12;
        float d  = data[b*NQ + q];
        float ax = es[q*3+0]*d + eb[q*3+0];
        float ay = es[q*3+1]*d + eb[q*3+1];
        float az = es[q*3+2]*d + eb[q*3+2];
        CM M;
        if (blk == 0)      M = mm(RZ(az), mm(RY(ay), RX(ax)));
        else if (blk == 1) M = mm(RY(ay), RX(ax));
        else               M = mm(RZ(az), RY(ay));
#pragma unroll
        for (int k = 0; k < 4; k++) gT1[blk][q][k] = M.m[k];

        float bias = (blk == 0) ? nb_z[q] : (blk == 1) ? nb_x[q] : nb_y[q];
        CM Mb = (blk == 0) ? RZ(bias) : (blk == 1) ? RX(bias) : RY(bias);
        const float* rr = rots + blk*(NQ*3) + q*3;
        CM M2 = mm(RZ(rr[2]), mm(RY(rr[1]), mm(RX(rr[0]), Mb)));
#pragma unroll
        for (int k = 0; k < 4; k++) gT2[blk][q][k] = M2.m[k];

        float ew = (blk == 0) ? ew_zz[q] : (blk == 1) ? ew_xx[q] : ew_yy[q];
        float h = 0.5f * eta[blk] * ew;
        float s, c; sincosf(h, &s, &c);
        sC[blk][q] = c; sS[blk][q] = s;
        if (blk == 0) sH0[q] = h;
    }
    __syncthreads();

    float2* cur  = ampA;
    float2* nxt  = ampB;
    float2* pcur = peerA;
    float2* pnxt = peerB;

    // ---- blk0: product-state init + fused ZZ phase ----
    {
        float2 prod = rank ? gT1[0][11][2] : gT1[0][11][0];
#pragma unroll
        for (int q = 0; q < 9; q++) {
            float2 f = ((t >> q) & 1) ? gT1[0][q][2] : gT1[0][q][0];
            prod = cxmul(prod, f);
        }
        constexpr unsigned XE0v[12] = {
            XEc(0,0), XEc(0,1), XEc(0,2),  XEc(0,3),
            XEc(0,4), XEc(0,5), XEc(0,6),  XEc(0,7),
            XEc(0,8), XEc(0,9), XEc(0,10), XEc(0,11)
        };
#pragma unroll
        for (int j = 0; j < 4; j++) {
            unsigned l = t + j*NT;
            float2 v = cxmul(prod, (j & 1) ? gT1[0][9][2]  : gT1[0][9][0]);
            v = cxmul(v,           (j & 2) ? gT1[0][10][2] : gT1[0][10][0]);
            unsigned k12 = l | (rank << 11);
            float phi = 0.0f;
#pragma unroll
            for (int e = 0; e < 12; e++)
                phi += par(k12 & XE0v[e]) ? sH0[e] : -sH0[e];
            float sp, cp; __sincosf(phi, &sp, &cp);
            cur[l] = make_float2(v.x*cp - v.y*sp, v.x*sp + v.y*cp);
        }
        __syncthreads();
    }
    // blk0 bias+rots locals (q11 deferred) — unchanged from champion
    sweepA1q<0>(gT2[0], cur, rank, t);
    quadSweep<0,5,6,true >(gT2[0], cur, rank, t);
    quadSweep<0,7,8,false>(gT2[0], cur, rank, t);

    // ======== block 1 ========
    cross1q<1>(gT2[0][11], gT1[1], cur, nxt, pcur, pnxt, cl, rank, t);
    quadSweep<1,9,10,true>(gT1[1], cur, rank, t);
    quadSweep<1,5,6 ,true>(gT1[1], cur, rank, t);
    quadSweep<1,7,8 ,true>(gT1[1], cur, rank, t);
    isingSweep<1,1,2,true ,true >(sC[1], sS[1], cur, rank, t);
    isingSweep<1,3,4,false,true >(sC[1], sS[1], cur, rank, t);
    isingSweep<1,5,6,false,false>(sC[1], sS[1], cur, rank, t);
    crossE<1>(sC[1], sS[1], gT2[1], cur, nxt, pcur, pnxt, cl, rank, t);
    quadSweep<1,9,10,true >(gT2[1], cur, rank, t);
    quadSweep<1,5,6 ,true >(gT2[1], cur, rank, t);
    quadSweep<1,7,8 ,false>(gT2[1], cur, rank, t);

    // ======== block 2 ========
    cross1q<2>(gT2[1][11], gT1[2], cur, nxt, pcur, pnxt, cl, rank, t);
    quadSweep<2,9,10,true>(gT1[2], cur, rank, t);
    quadSweep<2,5,6 ,true>(gT1[2], cur, rank, t);
    quadSweep<2,7,8 ,true>(gT1[2], cur, rank, t);
    isingSweep<2,1,2,true ,true >(sC[2], sS[2], cur, rank, t);
    isingSweep<2,3,4,false,true >(sC[2], sS[2], cur, rank, t);
    isingSweep<2,5,6,false,false>(sC[2], sS[2], cur, rank, t);
    crossE<2>(sC[2], sS[2], gT2[2], cur, nxt, pcur, pnxt, cl, rank, t);
    quadSweep<2,9,10,true >(gT2[2], cur, rank, t);
    quadSweep<2,5,6 ,true >(gT2[2], cur, rank, t);
    quadSweep<2,7,8 ,false>(gT2[2], cur, rank, t);

    // ---- final deferred bias(blk2)@q11 cross + measurement (fused) ----
    float acc[NQ];
#pragma unroll
    for (int i = 0; i < NQ; i++) acc[i] = 0.0f;
    {
        constexpr unsigned ma = m1c(2, 11);
        constexpr unsigned pm = ma & 0x7FFu;
        const float2* g = gT2[2][11];
        const float2 gd = rank ? g[3] : g[0];
        const float2 go = rank ? g[2] : g[1];
        constexpr unsigned RMv[12] = {
            RMc(0), RMc(1), RMc(2),  RMc(3),
            RMc(4), RMc(5), RMc(6),  RMc(7),
            RMc(8), RMc(9), RMc(10), RMc(11)
        };
        cl.sync();
#pragma unroll
        for (int j = 0; j < 4; j++) {
            unsigned l = t + j*NT;
            float2 pv = pcur[l ^ pm];
            float2 a = cur[l];
            float2 r;
            r.x = gd.x*a.x - gd.y*a.y + go.x*pv.x - go.y*pv.y;
            r.y = gd.x*a.y + gd.y*a.x + go.x*pv.y + go.y*pv.x;
            float pr = r.x*r.x + r.y*r.y;
#pragma unroll
            for (int i = 0; i < NQ; i++) {
                unsigned Rm = RMv[i];
                unsigned sg = (unsigned)par(l & (Rm & 0x7FFu));
                if (Rm >> 11) sg ^= rank;
                acc[i] += sg ? -pr : pr;
            }
        }
    }
#pragma unroll
    for (int off = 16; off > 0; off >>= 1)
#pragma unroll
        for (int i = 0; i < NQ; i++)
            acc[i] += __shfl_down_sync(0xffffffffu, acc[i], off);
    const int wid = t >> 5;
    if ((t & 31) == 0) {
#pragma unroll
        for (int i = 0; i < NQ; i++) red[wid][i] = acc[i];
    }
    __syncthreads();
    if (t < NQ) {
        float s = 0.0f;
#pragma unroll
        for (int w = 0; w < NT/32; w++) s += red[w][t];
        sums[t] = s;
    }
    __syncthreads();
    cl.sync();
    if (rank == 0 && t < NQ)
        out[b*NQ + t] = sums[t] + psums[t];
    cl.sync();
}

extern "C" void kernel_launch(void* const* d_in, const int* in_sizes, int n_in,
                              void* d_out, int out_size) {
    const float* data   = (const float*)d_in[0];
    const float* es     = (const float*)d_in[1];
    const float* eb     = (const float*)d_in[2];
    const float* eta    = (const float*)d_in[3];
    const float* ew_zz  = (const float*)d_in[4];
    const float* ew_xx  = (const float*)d_in[5];
    const float* ew_yy  = (const float*)d_in[6];
    const float* nb_z   = (const float*)d_in[7];
    const float* nb_x   = (const float*)d_in[8];
    const float* nb_y   = (const float*)d_in[9];
    const float* rots   = (const float*)d_in[10];
    float* out = (float*)d_out;

    int B = in_sizes[0] / NQ;   // 64
    qsim_kernel<<<B * 2, NT>>>(data, es, eb, eta, ew_zz, ew_xx, ew_yy,
                               nb_z, nb_x, nb_y, rots, out);
}